// round 15
// baseline (speedup 1.0000x reference)
#include <cuda_runtime.h>
#include <cuda_fp16.h>
#include <math.h>

#define NB   4
#define CH   16
#define HWSZ 65536
#define EPSV 1e-6f
#define LOG2E_T 14.4269504089f     // (1/TEMP) * log2(e)
#define LN2F    0.69314718056f

typedef unsigned long long u64;
typedef unsigned int u32;

__device__ float g_lp[1024];
__device__ unsigned int g_ctr = 0;

// ---------------- helpers ----------------
__device__ __forceinline__ u64 f2add(u64 a, u64 b) {
    u64 d; asm("add.rn.f32x2 %0,%1,%2;" : "=l"(d) : "l"(a), "l"(b)); return d;
}
__device__ __forceinline__ u64 pack2(float lo, float hi) {
    u64 d; asm("mov.b64 %0,{%1,%2};" : "=l"(d) : "f"(lo), "f"(hi)); return d;
}
__device__ __forceinline__ void unpack2(u64 v, float& lo, float& hi) {
    asm("mov.b64 {%0,%1},%2;" : "=f"(lo), "=f"(hi) : "l"(v));
}
__device__ __forceinline__ float ex2f(float x) {
    float r; asm("ex2.approx.ftz.f32 %0,%1;" : "=f"(r) : "f"(x)); return r;
}
// fp16 (half2) 16-dim dot: 8 HFMA2 in 2 chains, join, fold, 1 convert
__device__ __forceinline__ float dot16h(const u32 a[8], const u32 b[8]) {
    u32 p, q, r, rs, r2;
    asm("mul.rn.f16x2 %0,%1,%2;" : "=r"(p) : "r"(a[0]), "r"(b[0]));
    asm("mul.rn.f16x2 %0,%1,%2;" : "=r"(q) : "r"(a[1]), "r"(b[1]));
    asm("fma.rn.f16x2 %0,%1,%2,%3;" : "=r"(p) : "r"(a[2]), "r"(b[2]), "r"(p));
    asm("fma.rn.f16x2 %0,%1,%2,%3;" : "=r"(q) : "r"(a[3]), "r"(b[3]), "r"(q));
    asm("fma.rn.f16x2 %0,%1,%2,%3;" : "=r"(p) : "r"(a[4]), "r"(b[4]), "r"(p));
    asm("fma.rn.f16x2 %0,%1,%2,%3;" : "=r"(q) : "r"(a[5]), "r"(b[5]), "r"(q));
    asm("fma.rn.f16x2 %0,%1,%2,%3;" : "=r"(p) : "r"(a[6]), "r"(b[6]), "r"(p));
    asm("fma.rn.f16x2 %0,%1,%2,%3;" : "=r"(q) : "r"(a[7]), "r"(b[7]), "r"(q));
    asm("add.rn.f16x2 %0,%1,%2;" : "=r"(r) : "r"(p), "r"(q));
    asm("prmt.b32 %0,%1,%1,0x1032;" : "=r"(rs) : "r"(r));
    asm("add.rn.f16x2 %0,%1,%2;" : "=r"(r2) : "r"(r), "r"(rs));
    float f;
    asm("{.reg .b16 lo,hi; mov.b32 {lo,hi}, %1; cvt.f32.f16 %0, lo;}"
        : "=f"(f) : "r"(r2));
    return f;
}
// scale 8 half2 regs by splat constant (fp16)
__device__ __forceinline__ void scale16h(u32 h[8], u32 k2) {
#pragma unroll
    for (int i = 0; i < 8; i++)
        asm("mul.rn.f16x2 %0,%1,%2;" : "=r"(h[i]) : "r"(h[i]), "r"(k2));
}

// Chunk-split layout per row slot: [evenL 368 | evenH 368 | oddL 368 | oddH 368]
// (23 pixels per parity). Address = base + idx*16; H chunk at +368 immediate.
#define ROWB 1472
#define POFF 736                     // odd-parity offset within a row slot
#define CHNK 368                     // H-chunk offset within a parity
#define LROW 46                      // label ints per row slot
#define LPAR 23                      // odd-parity label offset

// load 16 halves (as 8 u32) from a parity sub-array
__device__ __forceinline__ void load16h(const char* pb, int idx, u32 h[8]) {
    const char* p = pb + (idx << 4);
    uint4 a = *(const uint4*)(p);
    uint4 b = *(const uint4*)(p + CHNK);
    h[0]=a.x; h[1]=a.y; h[2]=a.z; h[3]=a.w;
    h[4]=b.x; h[5]=b.y; h[6]=b.z; h[7]=b.w;
}

// ---- directional term for ONE center pixel (3x3 stencil inside the tile) ----
__device__ __forceinline__ float dirterm(const char* sF, const int* sLab,
                                         const int* __restrict__ labels,
                                         const int* __restrict__ dirs,
                                         const u32 cv[8], int srow, int xc,
                                         int pix) {
    float dt[NB]; bool mk[NB]; float S = 0.f;
#pragma unroll
    for (int k = 0; k < NB; k++) {
        int dik = dirs[(k * 2 + 0) * HWSZ + pix];
        int djk = dirs[(k * 2 + 1) * HWSZ + pix];
        int sl = srow + dik;
        int x  = xc + djk;
        u32 nv[8]; load16h(sF + sl * ROWB + (x & 1) * POFF, x >> 1, nv);
        dt[k] = dot16h(cv, nv);              // log2-scaled logit
        int lbn = sLab[sl * LROW + (x & 1) * LPAR + (x >> 1)];
        mk[k] = (labels[k * HWSZ + pix] == lbn);
        S += mk[k] ? ex2f(dt[k]) : 0.f;
    }
    float logS = __logf(S + EPSV);
    float s = 0.f;
#pragma unroll
    for (int k = 0; k < NB; k++)
        s += mk[k] ? (logS - LN2F * dt[k]) : __int_as_float(0x7f800000);
    return s;
}

// ---------------------------------------------------------------------------
// Single fused kernel. Block = (n, 8 center rows, 32-col slice), 64 threads,
// 2x2 quad per thread. Halo 18 rows x 46 cols -> 29.8 KB smem, 7 blocks/SM,
// grid 1024 = one near-balanced wave. Halo fill normalizes fp32 in-register.
// ---------------------------------------------------------------------------
__global__ void __launch_bounds__(64, 7)
k_local(const float* __restrict__ feat, const int* __restrict__ labels,
        const int* __restrict__ dirs, float* __restrict__ out) {
    extern __shared__ char sm[];
    char* sF   = sm;                      // 18 * 1472 = 26496 B
    int*  sLab = (int*)(sm + 18 * ROWB);  // 18 * 46 ints = 3312 B

    const int bx  = blockIdx.x;           // 0..1023
    const int n   = bx >> 8;
    const int rem = bx & 255;
    const int i0  = (rem >> 3) << 3;      // first center row (mult of 8)
    const int qc  = rem & 7;              // which 32-col slice
    const int cb  = qc * 32 - 8;          // tile base col (global)
    const int t   = threadIdx.x;

    // ---- fill halo: 18 rows x 46 cols; normalize+quantize inline ----
    {
        const float* fbase = feat + (size_t)n * CH * HWSZ;
#pragma unroll 1
        for (int k = 0; k < 13; k++) {
            int lin = t + (k << 6);           // need 828
            if (lin < 828) {
                int rr = lin / 46;
                int x  = lin - rr * 46;
                int row = i0 - 5 + rr;
                int g   = cb + x;
                if ((unsigned)row < 256u && (unsigned)g < 256u) {
                    const float* p = fbase + (row << 8) + g;
                    float v[CH]; float ss = 0.f;
#pragma unroll
                    for (int c = 0; c < CH; c++) {
                        v[c] = p[(size_t)c * HWSZ];
                        ss = fmaf(v[c], v[c], ss);
                    }
                    float inv = 1.0f / fmaxf(sqrtf(ss), 1e-12f);
                    u32 h[8];
#pragma unroll
                    for (int c2 = 0; c2 < 8; c2++) {
                        __half2 hh = __floats2half2_rn(v[c2*2] * inv,
                                                       v[c2*2+1] * inv);
                        h[c2] = *(u32*)&hh;
                    }
                    char* dst = sF + rr * ROWB + (x & 1) * POFF + ((x >> 1) << 4);
                    *(uint4*)(dst)        = make_uint4(h[0], h[1], h[2], h[3]);
                    *(uint4*)(dst + CHNK) = make_uint4(h[4], h[5], h[6], h[7]);
                }
            }
        }
        const int* ls = labels + n * HWSZ;
#pragma unroll
        for (int k = 0; k < 13; k++) {
            int lin = t + (k << 6);           // need 828
            if (lin < 828) {
                int rr = lin / 46;
                int x  = lin - rr * 46;
                int row = i0 - 5 + rr;
                int g   = cb + x;
                bool ok = ((unsigned)row < 256u) && ((unsigned)g < 256u);
                sLab[rr * LROW + (x & 1) * LPAR + (x >> 1)] =
                    ok ? ls[(row << 8) + g] : (int)0x80000000;
            }
        }
    }
    __syncthreads();

    const int rp = t >> 4;               // 0..3
    const int cp = t & 15;               // col pair 0..15
    const int tc = cp + 4;
    const int sA = 2 * rp + 5;
    const int sB = sA + 1;

    u32 cvAe[8], cvAo[8], cvBe[8], cvBo[8];
    load16h(sF + sA * ROWB,        tc, cvAe);
    load16h(sF + sA * ROWB + POFF, tc, cvAo);
    load16h(sF + sB * ROWB,        tc, cvBe);
    load16h(sF + sB * ROWB + POFF, tc, cvBo);
    __half2 kt = __floats2half2_rn(LOG2E_T, LOG2E_T);
    u32 kt2 = *(u32*)&kt;
    scale16h(cvAe, kt2); scale16h(cvAo, kt2);
    scale16h(cvBe, kt2); scale16h(cvBo, kt2);
    const int clAe = sLab[sA * LROW + tc];
    const int clAo = sLab[sA * LROW + LPAR + tc];
    const int clBe = sLab[sB * LROW + tc];
    const int clBo = sLab[sB * LROW + LPAR + tc];

    u64 SDAe = 0, SDAo = 0, SDBe = 0, SDBo = 0;   // packed {S, D}
    int MAe = 0, MAo = 0, MBe = 0, MBo = 0;

    // ================= v = 0 peel: A-centers only =================
    {
        int s   = 2 * rp;                  // slot 0..6
        int row = i0 - 5 + s;
        if (row >= 0) {
            const char* rowE = sF + s * ROWB;
            const char* rowO = rowE + POFF;
            const int* labE = sLab + s * LROW;
            const int* labO = labE + LPAR;
#pragma unroll
            for (int u = 0; u < 6; u++) {
                int e = cp + 2 + u;
                u32 nv[8]; load16h(rowE, e, nv);
                int lb = labE[e];
                float dAo = dot16h(cvAo, nv);
                float eAo = ex2f(dAo);
                if (lb == clAo) { SDAo = f2add(SDAo, pack2(eAo, dAo)); MAo++; }
                if (u != 5) {
                    float dAe = dot16h(cvAe, nv);
                    float eAe = ex2f(dAe);
                    if (lb == clAe) { SDAe = f2add(SDAe, pack2(eAe, dAe)); MAe++; }
                }
            }
#pragma unroll
            for (int u = 0; u < 6; u++) {
                int o = cp + 1 + u;
                u32 nv[8]; load16h(rowO, o, nv);
                int lb = labO[o];
                float dAe = dot16h(cvAe, nv);
                float eAe = ex2f(dAe);
                if (lb == clAe) { SDAe = f2add(SDAe, pack2(eAe, dAe)); MAe++; }
                if (u != 0) {
                    float dAo = dot16h(cvAo, nv);
                    float eAo = ex2f(dAo);
                    if (lb == clAo) { SDAo = f2add(SDAo, pack2(eAo, dAo)); MAo++; }
                }
            }
        }
    }

    // ================= main loop v = 1..10: all four centers =================
#pragma unroll 1
    for (int v = 1; v <= 10; v++) {
        int s   = 2 * rp + v;
        int row = i0 - 5 + s;
        if ((unsigned)row >= 256u) continue;
        const char* rowE = sF + s * ROWB;
        const char* rowO = rowE + POFF;
        const int* labE = sLab + s * LROW;
        const int* labO = labE + LPAR;

        // even-pixel neighbors
#pragma unroll
        for (int u = 0; u < 6; u++) {
            int e = cp + 2 + u;
            u32 nv[8]; load16h(rowE, e, nv);
            int lb = labE[e];
            {
                float dAo = dot16h(cvAo, nv);
                float dBo = dot16h(cvBo, nv);
                float eAo = ex2f(dAo), eBo = ex2f(dBo);
                if (lb == clAo) { SDAo = f2add(SDAo, pack2(eAo, dAo)); MAo++; }
                if (lb == clBo) { SDBo = f2add(SDBo, pack2(eBo, dBo)); MBo++; }
            }
            if (u != 5) {
                float dAe = dot16h(cvAe, nv);
                float dBe = dot16h(cvBe, nv);
                float eAe = ex2f(dAe), eBe = ex2f(dBe);
                if (lb == clAe) { SDAe = f2add(SDAe, pack2(eAe, dAe)); MAe++; }
                if (lb == clBe) { SDBe = f2add(SDBe, pack2(eBe, dBe)); MBe++; }
            }
        }
        // odd-pixel neighbors
#pragma unroll
        for (int u = 0; u < 6; u++) {
            int o = cp + 1 + u;
            u32 nv[8]; load16h(rowO, o, nv);
            int lb = labO[o];
            {
                float dAe = dot16h(cvAe, nv);
                float dBe = dot16h(cvBe, nv);
                float eAe = ex2f(dAe), eBe = ex2f(dBe);
                if (lb == clAe) { SDAe = f2add(SDAe, pack2(eAe, dAe)); MAe++; }
                if (lb == clBe) { SDBe = f2add(SDBe, pack2(eBe, dBe)); MBe++; }
            }
            if (u != 0) {
                float dAo = dot16h(cvAo, nv);
                float dBo = dot16h(cvBo, nv);
                float eAo = ex2f(dAo), eBo = ex2f(dBo);
                if (lb == clAo) { SDAo = f2add(SDAo, pack2(eAo, dAo)); MAo++; }
                if (lb == clBo) { SDBo = f2add(SDBo, pack2(eBo, dBo)); MBo++; }
            }
        }
    }

    // ================= v = 11 peel: B-centers only =================
    {
        int s   = 2 * rp + 11;             // slot 11..17
        int row = i0 - 5 + s;
        if (row < 256) {
            const char* rowE = sF + s * ROWB;
            const char* rowO = rowE + POFF;
            const int* labE = sLab + s * LROW;
            const int* labO = labE + LPAR;
#pragma unroll
            for (int u = 0; u < 6; u++) {
                int e = cp + 2 + u;
                u32 nv[8]; load16h(rowE, e, nv);
                int lb = labE[e];
                float dBo = dot16h(cvBo, nv);
                float eBo = ex2f(dBo);
                if (lb == clBo) { SDBo = f2add(SDBo, pack2(eBo, dBo)); MBo++; }
                if (u != 5) {
                    float dBe = dot16h(cvBe, nv);
                    float eBe = ex2f(dBe);
                    if (lb == clBe) { SDBe = f2add(SDBe, pack2(eBe, dBe)); MBe++; }
                }
            }
#pragma unroll
            for (int u = 0; u < 6; u++) {
                int o = cp + 1 + u;
                u32 nv[8]; load16h(rowO, o, nv);
                int lb = labO[o];
                float dBe = dot16h(cvBe, nv);
                float eBe = ex2f(dBe);
                if (lb == clBe) { SDBe = f2add(SDBe, pack2(eBe, dBe)); MBe++; }
                if (u != 0) {
                    float dBo = dot16h(cvBo, nv);
                    float eBo = ex2f(dBo);
                    if (lb == clBo) { SDBo = f2add(SDBo, pack2(eBo, dBo)); MBo++; }
                }
            }
        }
    }

    float SAe, DAe, SAo, DAo, SBe, DBe, SBo, DBo;
    unpack2(SDAe, SAe, DAe);  unpack2(SDAo, SAo, DAo);
    unpack2(SDBe, SBe, DBe);  unpack2(SDBo, SBo, DBo);

    float cAe = fmaf((float)MAe, __logf(SAe + EPSV), -LN2F * DAe);
    float cAo = fmaf((float)MAo, __logf(SAo + EPSV), -LN2F * DAo);
    float cBe = fmaf((float)MBe, __logf(SBe + EPSV), -LN2F * DBe);
    float cBo = fmaf((float)MBo, __logf(SBo + EPSV), -LN2F * DBo);
    int ciA = i0 + 2 * rp, ciB = ciA + 1;
    int j0  = qc * 32 + 2 * cp, j1 = j0 + 1;
    float chA = (float)(11 - max(0, 5 - ciA) - max(0, ciA - 250));
    float chB = (float)(11 - max(0, 5 - ciB) - max(0, ciB - 250));
    float cw0 = (float)(11 - max(0, 5 - j0)  - max(0, j0  - 250));
    float cw1 = (float)(11 - max(0, 5 - j1)  - max(0, j1  - 250));
    float val = (cAe / (chA * cw0) + cAo / (chA * cw1)
               + cBe / (chB * cw0) + cBo / (chB * cw1)) * (1.0f / (4.0f * 65536.0f));

    // ---- directional term for this thread's 4 pixels (3x3 stencil in tile) --
    {
        float ds = dirterm(sF, sLab, labels, dirs, cvAe, sA, 2*cp + 8, (ciA << 8) + j0)
                 + dirterm(sF, sLab, labels, dirs, cvAo, sA, 2*cp + 9, (ciA << 8) + j1)
                 + dirterm(sF, sLab, labels, dirs, cvBe, sB, 2*cp + 8, (ciB << 8) + j0)
                 + dirterm(sF, sLab, labels, dirs, cvBo, sB, 2*cp + 9, (ciB << 8) + j1);
        val += ds * (1.0f / (16.0f * 65536.0f));
    }

    // ---- block reduce (2 warps) + last-finishing block folds the final sum --
    __shared__ float wred[2];
    __shared__ bool  slast;
#pragma unroll
    for (int o = 16; o > 0; o >>= 1) val += __shfl_down_sync(0xffffffffu, val, o);
    if ((t & 31) == 0) wred[t >> 5] = val;
    __syncthreads();
    if (t == 0) {
        g_lp[bx] = wred[0] + wred[1];
        __threadfence();
        unsigned old = atomicAdd(&g_ctr, 1u);
        slast = (old == 1023u);
    }
    __syncthreads();

    if (slast) {   // deterministic final reduction over 1024 partials
        float v = 0.f;
#pragma unroll
        for (int k = 0; k < 16; k++) v += g_lp[t + (k << 6)];
#pragma unroll
        for (int o = 16; o > 0; o >>= 1) v += __shfl_down_sync(0xffffffffu, v, o);
        if ((t & 31) == 0) wred[t >> 5] = v;
        __syncthreads();
        if (t == 0) {
            out[0] = wred[0] + wred[1];
            g_ctr = 0;   // reset for next graph replay
        }
    }
}

// ---------------------------------------------------------------------------
extern "C" void kernel_launch(void* const* d_in, const int* in_sizes, int n_in,
                              void* d_out, int out_size) {
    const float* feat   = (const float*)d_in[0];
    const int*   labels = (const int*)d_in[1];
    const int*   dirs   = (const int*)d_in[2];
    float* out = (float*)d_out;

    const int smem = 18 * ROWB + 18 * LROW * 4;   // 26496 + 3312 = 29808 B
    cudaFuncSetAttribute(k_local, cudaFuncAttributeMaxDynamicSharedMemorySize, smem);

    k_local<<<1024, 64, smem>>>(feat, labels, dirs, out);
}

// round 16
// speedup vs baseline: 1.0802x; 1.0802x over previous
#include <cuda_runtime.h>
#include <cuda_fp16.h>
#include <math.h>

#define NB   4
#define CH   16
#define HWSZ 65536
#define EPSV 1e-6f
#define LOG2E_T 14.4269504089f     // (1/TEMP) * log2(e)
#define LN2F    0.69314718056f

typedef unsigned long long u64;
typedef unsigned int u32;

__device__ float g_lp[512];
__device__ unsigned int g_ctr = 0;

// ---------------- helpers ----------------
__device__ __forceinline__ u64 f2add(u64 a, u64 b) {
    u64 d; asm("add.rn.f32x2 %0,%1,%2;" : "=l"(d) : "l"(a), "l"(b)); return d;
}
__device__ __forceinline__ u64 pack2(float lo, float hi) {
    u64 d; asm("mov.b64 %0,{%1,%2};" : "=l"(d) : "f"(lo), "f"(hi)); return d;
}
__device__ __forceinline__ void unpack2(u64 v, float& lo, float& hi) {
    asm("mov.b64 {%0,%1},%2;" : "=f"(lo), "=f"(hi) : "l"(v));
}
__device__ __forceinline__ float ex2f(float x) {
    float r; asm("ex2.approx.ftz.f32 %0,%1;" : "=f"(r) : "f"(x)); return r;
}
// fp16 (half2) 16-dim dot: SINGLE 8-op HFMA2 chain, fold, 1 convert.
// (ILP comes from 4 concurrent dots per neighbor, not intra-dot chains.)
__device__ __forceinline__ float dot16h(const u32 a[8], const u32 b[8]) {
    u32 p, rs, r2;
    asm("mul.rn.f16x2 %0,%1,%2;" : "=r"(p) : "r"(a[0]), "r"(b[0]));
    asm("fma.rn.f16x2 %0,%1,%2,%3;" : "=r"(p) : "r"(a[1]), "r"(b[1]), "r"(p));
    asm("fma.rn.f16x2 %0,%1,%2,%3;" : "=r"(p) : "r"(a[2]), "r"(b[2]), "r"(p));
    asm("fma.rn.f16x2 %0,%1,%2,%3;" : "=r"(p) : "r"(a[3]), "r"(b[3]), "r"(p));
    asm("fma.rn.f16x2 %0,%1,%2,%3;" : "=r"(p) : "r"(a[4]), "r"(b[4]), "r"(p));
    asm("fma.rn.f16x2 %0,%1,%2,%3;" : "=r"(p) : "r"(a[5]), "r"(b[5]), "r"(p));
    asm("fma.rn.f16x2 %0,%1,%2,%3;" : "=r"(p) : "r"(a[6]), "r"(b[6]), "r"(p));
    asm("fma.rn.f16x2 %0,%1,%2,%3;" : "=r"(p) : "r"(a[7]), "r"(b[7]), "r"(p));
    asm("prmt.b32 %0,%1,%1,0x1032;" : "=r"(rs) : "r"(p));
    asm("add.rn.f16x2 %0,%1,%2;" : "=r"(r2) : "r"(p), "r"(rs));
    float f;
    asm("{.reg .b16 lo,hi; mov.b32 {lo,hi}, %1; cvt.f32.f16 %0, lo;}"
        : "=f"(f) : "r"(r2));
    return f;
}
// scale 8 half2 regs by splat constant (fp16)
__device__ __forceinline__ void scale16h(u32 h[8], u32 k2) {
#pragma unroll
    for (int i = 0; i < 8; i++)
        asm("mul.rn.f16x2 %0,%1,%2;" : "=r"(h[i]) : "r"(h[i]), "r"(k2));
}

// Chunk-split layout per row slot: [evenL 608 | evenH 608 | oddL 608 | oddH 608]
// (38 pixels per parity, 76-col halo). Address = base + idx*16; H at +608.
#define ROWB 2432
#define POFF 1216                    // odd-parity offset within a row slot
#define CHNK 608                     // H-chunk offset within a parity
#define LROW 76                      // label ints per row slot
#define LPAR 38                      // odd-parity label offset

// load 16 halves (as 8 u32) from a parity sub-array
__device__ __forceinline__ void load16h(const char* pb, int idx, u32 h[8]) {
    const char* p = pb + (idx << 4);
    uint4 a = *(const uint4*)(p);
    uint4 b = *(const uint4*)(p + CHNK);
    h[0]=a.x; h[1]=a.y; h[2]=a.z; h[3]=a.w;
    h[4]=b.x; h[5]=b.y; h[6]=b.z; h[7]=b.w;
}

// ---- directional term for ONE center pixel (3x3 stencil inside the tile) ----
__device__ __forceinline__ float dirterm(const char* sF, const int* sLab,
                                         const int* __restrict__ labels,
                                         const int* __restrict__ dirs,
                                         const u32 cv[8], int srow, int xc,
                                         int pix) {
    float dt[NB]; bool mk[NB]; float S = 0.f;
#pragma unroll
    for (int k = 0; k < NB; k++) {
        int dik = dirs[(k * 2 + 0) * HWSZ + pix];
        int djk = dirs[(k * 2 + 1) * HWSZ + pix];
        int sl = srow + dik;
        int x  = xc + djk;
        u32 nv[8]; load16h(sF + sl * ROWB + (x & 1) * POFF, x >> 1, nv);
        dt[k] = dot16h(cv, nv);              // log2-scaled logit
        int lbn = sLab[sl * LROW + (x & 1) * LPAR + (x >> 1)];
        mk[k] = (labels[k * HWSZ + pix] == lbn);
        S += mk[k] ? ex2f(dt[k]) : 0.f;
    }
    float logS = __logf(S + EPSV);
    float s = 0.f;
#pragma unroll
    for (int k = 0; k < NB; k++)
        s += mk[k] ? (logS - LN2F * dt[k]) : __int_as_float(0x7f800000);
    return s;
}

// ---------------------------------------------------------------------------
// Single fused kernel. Block = (n, 8 center rows, 64-col quarter), 128 thr,
// 2x2 quad per thread. Halo 18 rows x 76 cols -> 49.2 KB smem, 4 blocks/SM.
// Halo fill normalizes raw fp32 features in-register (== old k_norm math).
// ---------------------------------------------------------------------------
__global__ void __launch_bounds__(128, 4)
k_local(const float* __restrict__ feat, const int* __restrict__ labels,
        const int* __restrict__ dirs, float* __restrict__ out) {
    extern __shared__ char sm[];
    char* sF   = sm;                      // 18 * 2432 = 43776 B
    int*  sLab = (int*)(sm + 18 * ROWB);  // 18 * 76 ints = 5472 B

    const int bx  = blockIdx.x;           // 0..511
    const int n   = bx >> 7;
    const int rem = bx & 127;
    const int i0  = (rem >> 2) << 3;      // first center row (mult of 8)
    const int hq  = rem & 3;              // which 64-col quarter
    const int cb  = hq * 64 - 6;          // tile base col (global)
    const int t   = threadIdx.x;

    // ---- fill halo: 18 rows x 76 cols; normalize+quantize inline ----
    {
        const float* fbase = feat + (size_t)n * CH * HWSZ;
#pragma unroll 1
        for (int k = 0; k < 11; k++) {
            int lin = t + (k << 7);           // need 1368
            if (lin < 1368) {
                int rr = lin / 76;
                int x  = lin - rr * 76;
                int row = i0 - 5 + rr;
                int g   = cb + x;
                if ((unsigned)row < 256u && (unsigned)g < 256u) {
                    const float* p = fbase + (row << 8) + g;
                    float v[CH]; float ss = 0.f;
#pragma unroll
                    for (int c = 0; c < CH; c++) {
                        v[c] = p[(size_t)c * HWSZ];
                        ss = fmaf(v[c], v[c], ss);
                    }
                    float inv = 1.0f / fmaxf(sqrtf(ss), 1e-12f);
                    u32 h[8];
#pragma unroll
                    for (int c2 = 0; c2 < 8; c2++) {
                        __half2 hh = __floats2half2_rn(v[c2*2] * inv,
                                                       v[c2*2+1] * inv);
                        h[c2] = *(u32*)&hh;
                    }
                    char* dst = sF + rr * ROWB + (x & 1) * POFF + ((x >> 1) << 4);
                    *(uint4*)(dst)        = make_uint4(h[0], h[1], h[2], h[3]);
                    *(uint4*)(dst + CHNK) = make_uint4(h[4], h[5], h[6], h[7]);
                }
            }
        }
        const int* ls = labels + n * HWSZ;
#pragma unroll
        for (int k = 0; k < 11; k++) {
            int lin = t + (k << 7);           // need 1368
            if (lin < 1368) {
                int rr = lin / 76;
                int x  = lin - rr * 76;
                int row = i0 - 5 + rr;
                int g   = cb + x;
                bool ok = ((unsigned)row < 256u) && ((unsigned)g < 256u);
                sLab[rr * LROW + (x & 1) * LPAR + (x >> 1)] =
                    ok ? ls[(row << 8) + g] : (int)0x80000000;
            }
        }
    }
    __syncthreads();

    const int rp = t >> 5;               // 0..3 (warp-uniform)
    const int cp = t & 31;               // col pair 0..31
    const int tc = cp + 3;               // center parity index
    const int sA = 2 * rp + 5;
    const int sB = sA + 1;

    u32 cvAe[8], cvAo[8], cvBe[8], cvBo[8];
    load16h(sF + sA * ROWB,        tc, cvAe);
    load16h(sF + sA * ROWB + POFF, tc, cvAo);
    load16h(sF + sB * ROWB,        tc, cvBe);
    load16h(sF + sB * ROWB + POFF, tc, cvBo);
    __half2 kt = __floats2half2_rn(LOG2E_T, LOG2E_T);
    u32 kt2 = *(u32*)&kt;
    scale16h(cvAe, kt2); scale16h(cvAo, kt2);
    scale16h(cvBe, kt2); scale16h(cvBo, kt2);
    const int clAe = sLab[sA * LROW + tc];
    const int clAo = sLab[sA * LROW + LPAR + tc];
    const int clBe = sLab[sB * LROW + tc];
    const int clBo = sLab[sB * LROW + LPAR + tc];

    u64 SDAe = 0, SDAo = 0, SDBe = 0, SDBo = 0;   // packed {S, D}
    int MAe = 0, MAo = 0, MBe = 0, MBo = 0;

    // ================= v = 0 peel: A-centers only =================
    {
        int s   = 2 * rp;                  // slot 0..6
        int row = i0 - 5 + s;
        if (row >= 0) {                    // warp-uniform
            const char* rowE = sF + s * ROWB;
            const char* rowO = rowE + POFF;
            const int* labE = sLab + s * LROW;
            const int* labO = labE + LPAR;
#pragma unroll
            for (int u = 0; u < 6; u++) {
                int e = cp + 1 + u;
                u32 nv[8]; load16h(rowE, e, nv);
                int lb = labE[e];
                float dAo = dot16h(cvAo, nv);
                float eAo = ex2f(dAo);
                if (lb == clAo) { SDAo = f2add(SDAo, pack2(eAo, dAo)); MAo++; }
                if (u != 5) {
                    float dAe = dot16h(cvAe, nv);
                    float eAe = ex2f(dAe);
                    if (lb == clAe) { SDAe = f2add(SDAe, pack2(eAe, dAe)); MAe++; }
                }
            }
#pragma unroll
            for (int u = 0; u < 6; u++) {
                int o = cp + u;
                u32 nv[8]; load16h(rowO, o, nv);
                int lb = labO[o];
                float dAe = dot16h(cvAe, nv);
                float eAe = ex2f(dAe);
                if (lb == clAe) { SDAe = f2add(SDAe, pack2(eAe, dAe)); MAe++; }
                if (u != 0) {
                    float dAo = dot16h(cvAo, nv);
                    float eAo = ex2f(dAo);
                    if (lb == clAo) { SDAo = f2add(SDAo, pack2(eAo, dAo)); MAo++; }
                }
            }
        }
    }

    // ================= main loop v = 1..10: all four centers =================
#pragma unroll 1
    for (int v = 1; v <= 10; v++) {
        int s   = 2 * rp + v;
        int row = i0 - 5 + s;
        if ((unsigned)row >= 256u) continue;   // warp-uniform
        const char* rowE = sF + s * ROWB;
        const char* rowO = rowE + POFF;
        const int* labE = sLab + s * LROW;
        const int* labO = labE + LPAR;

        // even-pixel neighbors
#pragma unroll
        for (int u = 0; u < 6; u++) {
            int e = cp + 1 + u;
            u32 nv[8]; load16h(rowE, e, nv);
            int lb = labE[e];
            {
                float dAo = dot16h(cvAo, nv);
                float dBo = dot16h(cvBo, nv);
                float eAo = ex2f(dAo), eBo = ex2f(dBo);
                if (lb == clAo) { SDAo = f2add(SDAo, pack2(eAo, dAo)); MAo++; }
                if (lb == clBo) { SDBo = f2add(SDBo, pack2(eBo, dBo)); MBo++; }
            }
            if (u != 5) {
                float dAe = dot16h(cvAe, nv);
                float dBe = dot16h(cvBe, nv);
                float eAe = ex2f(dAe), eBe = ex2f(dBe);
                if (lb == clAe) { SDAe = f2add(SDAe, pack2(eAe, dAe)); MAe++; }
                if (lb == clBe) { SDBe = f2add(SDBe, pack2(eBe, dBe)); MBe++; }
            }
        }
        // odd-pixel neighbors
#pragma unroll
        for (int u = 0; u < 6; u++) {
            int o = cp + u;
            u32 nv[8]; load16h(rowO, o, nv);
            int lb = labO[o];
            {
                float dAe = dot16h(cvAe, nv);
                float dBe = dot16h(cvBe, nv);
                float eAe = ex2f(dAe), eBe = ex2f(dBe);
                if (lb == clAe) { SDAe = f2add(SDAe, pack2(eAe, dAe)); MAe++; }
                if (lb == clBe) { SDBe = f2add(SDBe, pack2(eBe, dBe)); MBe++; }
            }
            if (u != 0) {
                float dAo = dot16h(cvAo, nv);
                float dBo = dot16h(cvBo, nv);
                float eAo = ex2f(dAo), eBo = ex2f(dBo);
                if (lb == clAo) { SDAo = f2add(SDAo, pack2(eAo, dAo)); MAo++; }
                if (lb == clBo) { SDBo = f2add(SDBo, pack2(eBo, dBo)); MBo++; }
            }
        }
    }

    // ================= v = 11 peel: B-centers only =================
    {
        int s   = 2 * rp + 11;             // slot 11..17
        int row = i0 - 5 + s;
        if (row < 256) {                   // warp-uniform
            const char* rowE = sF + s * ROWB;
            const char* rowO = rowE + POFF;
            const int* labE = sLab + s * LROW;
            const int* labO = labE + LPAR;
#pragma unroll
            for (int u = 0; u < 6; u++) {
                int e = cp + 1 + u;
                u32 nv[8]; load16h(rowE, e, nv);
                int lb = labE[e];
                float dBo = dot16h(cvBo, nv);
                float eBo = ex2f(dBo);
                if (lb == clBo) { SDBo = f2add(SDBo, pack2(eBo, dBo)); MBo++; }
                if (u != 5) {
                    float dBe = dot16h(cvBe, nv);
                    float eBe = ex2f(dBe);
                    if (lb == clBe) { SDBe = f2add(SDBe, pack2(eBe, dBe)); MBe++; }
                }
            }
#pragma unroll
            for (int u = 0; u < 6; u++) {
                int o = cp + u;
                u32 nv[8]; load16h(rowO, o, nv);
                int lb = labO[o];
                float dBe = dot16h(cvBe, nv);
                float eBe = ex2f(dBe);
                if (lb == clBe) { SDBe = f2add(SDBe, pack2(eBe, dBe)); MBe++; }
                if (u != 0) {
                    float dBo = dot16h(cvBo, nv);
                    float eBo = ex2f(dBo);
                    if (lb == clBo) { SDBo = f2add(SDBo, pack2(eBo, dBo)); MBo++; }
                }
            }
        }
    }

    float SAe, DAe, SAo, DAo, SBe, DBe, SBo, DBo;
    unpack2(SDAe, SAe, DAe);  unpack2(SDAo, SAo, DAo);
    unpack2(SDBe, SBe, DBe);  unpack2(SDBo, SBo, DBo);

    float cAe = fmaf((float)MAe, __logf(SAe + EPSV), -LN2F * DAe);
    float cAo = fmaf((float)MAo, __logf(SAo + EPSV), -LN2F * DAo);
    float cBe = fmaf((float)MBe, __logf(SBe + EPSV), -LN2F * DBe);
    float cBo = fmaf((float)MBo, __logf(SBo + EPSV), -LN2F * DBo);
    int ciA = i0 + 2 * rp, ciB = ciA + 1;
    int j0  = hq * 64 + 2 * cp, j1 = j0 + 1;
    float chA = (float)(11 - max(0, 5 - ciA) - max(0, ciA - 250));
    float chB = (float)(11 - max(0, 5 - ciB) - max(0, ciB - 250));
    float cw0 = (float)(11 - max(0, 5 - j0)  - max(0, j0  - 250));
    float cw1 = (float)(11 - max(0, 5 - j1)  - max(0, j1  - 250));
    float val = (cAe / (chA * cw0) + cAo / (chA * cw1)
               + cBe / (chB * cw0) + cBo / (chB * cw1)) * (1.0f / (4.0f * 65536.0f));

    // ---- directional term for this thread's 4 pixels (3x3 stencil in tile) --
    {
        float ds = dirterm(sF, sLab, labels, dirs, cvAe, sA, 2*cp + 6, (ciA << 8) + j0)
                 + dirterm(sF, sLab, labels, dirs, cvAo, sA, 2*cp + 7, (ciA << 8) + j1)
                 + dirterm(sF, sLab, labels, dirs, cvBe, sB, 2*cp + 6, (ciB << 8) + j0)
                 + dirterm(sF, sLab, labels, dirs, cvBo, sB, 2*cp + 7, (ciB << 8) + j1);
        val += ds * (1.0f / (16.0f * 65536.0f));
    }

    // ---- block reduce + last-finishing block folds the final sum ----
    __shared__ float wred[4];
    __shared__ bool  slast;
#pragma unroll
    for (int o = 16; o > 0; o >>= 1) val += __shfl_down_sync(0xffffffffu, val, o);
    if ((t & 31) == 0) wred[t >> 5] = val;
    __syncthreads();
    if (t == 0) {
        g_lp[bx] = (wred[0] + wred[1]) + (wred[2] + wred[3]);
        __threadfence();
        unsigned old = atomicAdd(&g_ctr, 1u);
        slast = (old == 511u);
    }
    __syncthreads();

    if (slast) {   // deterministic final reduction over 512 partials
        float v = g_lp[t] + g_lp[t + 128] + g_lp[t + 256] + g_lp[t + 384];
#pragma unroll
        for (int o = 16; o > 0; o >>= 1) v += __shfl_down_sync(0xffffffffu, v, o);
        if ((t & 31) == 0) wred[t >> 5] = v;
        __syncthreads();
        if (t == 0) {
            out[0] = (wred[0] + wred[1]) + (wred[2] + wred[3]);
            g_ctr = 0;   // reset for next graph replay
        }
    }
}

// ---------------------------------------------------------------------------
extern "C" void kernel_launch(void* const* d_in, const int* in_sizes, int n_in,
                              void* d_out, int out_size) {
    const float* feat   = (const float*)d_in[0];
    const int*   labels = (const int*)d_in[1];
    const int*   dirs   = (const int*)d_in[2];
    float* out = (float*)d_out;

    const int smem = 18 * ROWB + 18 * LROW * 4;   // 43776 + 5472 = 49248 B
    cudaFuncSetAttribute(k_local, cudaFuncAttributeMaxDynamicSharedMemorySize, smem);

    k_local<<<512, 128, smem>>>(feat, labels, dirs, out);
}

// round 17
// speedup vs baseline: 1.0914x; 1.0104x over previous
#include <cuda_runtime.h>
#include <cuda_fp16.h>
#include <math.h>

#define NB   4
#define CH   16
#define HWSZ 65536
#define EPSV 1e-6f
#define LOG2E_T 14.4269504089f     // (1/TEMP) * log2(e)
#define LN2F    0.69314718056f

typedef unsigned long long u64;
typedef unsigned int u32;

__device__ float g_lp[512];
__device__ unsigned int g_ctr = 0;

// ---------------- helpers ----------------
__device__ __forceinline__ u64 f2add(u64 a, u64 b) {
    u64 d; asm("add.rn.f32x2 %0,%1,%2;" : "=l"(d) : "l"(a), "l"(b)); return d;
}
__device__ __forceinline__ u64 pack2(float lo, float hi) {
    u64 d; asm("mov.b64 %0,{%1,%2};" : "=l"(d) : "f"(lo), "f"(hi)); return d;
}
__device__ __forceinline__ void unpack2(u64 v, float& lo, float& hi) {
    asm("mov.b64 {%0,%1},%2;" : "=f"(lo), "=f"(hi) : "l"(v));
}
__device__ __forceinline__ float ex2f(float x) {
    float r; asm("ex2.approx.ftz.f32 %0,%1;" : "=f"(r) : "f"(x)); return r;
}
// fp16 (half2) 16-dim dot: SINGLE 8-op HFMA2 chain, fold, 1 convert.
// (ILP comes from concurrent dots across neighbors, not intra-dot chains.)
__device__ __forceinline__ float dot16h(const u32 a[8], const u32 b[8]) {
    u32 p, rs, r2;
    asm("mul.rn.f16x2 %0,%1,%2;" : "=r"(p) : "r"(a[0]), "r"(b[0]));
    asm("fma.rn.f16x2 %0,%1,%2,%3;" : "=r"(p) : "r"(a[1]), "r"(b[1]), "r"(p));
    asm("fma.rn.f16x2 %0,%1,%2,%3;" : "=r"(p) : "r"(a[2]), "r"(b[2]), "r"(p));
    asm("fma.rn.f16x2 %0,%1,%2,%3;" : "=r"(p) : "r"(a[3]), "r"(b[3]), "r"(p));
    asm("fma.rn.f16x2 %0,%1,%2,%3;" : "=r"(p) : "r"(a[4]), "r"(b[4]), "r"(p));
    asm("fma.rn.f16x2 %0,%1,%2,%3;" : "=r"(p) : "r"(a[5]), "r"(b[5]), "r"(p));
    asm("fma.rn.f16x2 %0,%1,%2,%3;" : "=r"(p) : "r"(a[6]), "r"(b[6]), "r"(p));
    asm("fma.rn.f16x2 %0,%1,%2,%3;" : "=r"(p) : "r"(a[7]), "r"(b[7]), "r"(p));
    asm("prmt.b32 %0,%1,%1,0x1032;" : "=r"(rs) : "r"(p));
    asm("add.rn.f16x2 %0,%1,%2;" : "=r"(r2) : "r"(p), "r"(rs));
    float f;
    asm("{.reg .b16 lo,hi; mov.b32 {lo,hi}, %1; cvt.f32.f16 %0, lo;}"
        : "=f"(f) : "r"(r2));
    return f;
}
// scale 8 half2 regs by splat constant (fp16)
__device__ __forceinline__ void scale16h(u32 h[8], u32 k2) {
#pragma unroll
    for (int i = 0; i < 8; i++)
        asm("mul.rn.f16x2 %0,%1,%2;" : "=r"(h[i]) : "r"(h[i]), "r"(k2));
}

// Chunk-split layout per row slot: [evenL 608 | evenH 608 | oddL 608 | oddH 608]
// (38 pixels per parity, 76-col halo). Address = base + idx*16; H at +608.
#define ROWB 2432
#define POFF 1216                    // odd-parity offset within a row slot
#define CHNK 608                     // H-chunk offset within a parity
#define LROW 76                      // label ints per row slot
#define LPAR 38                      // odd-parity label offset

// load 16 halves (as 8 u32) from a parity sub-array
__device__ __forceinline__ void load16h(const char* pb, int idx, u32 h[8]) {
    const char* p = pb + (idx << 4);
    uint4 a = *(const uint4*)(p);
    uint4 b = *(const uint4*)(p + CHNK);
    h[0]=a.x; h[1]=a.y; h[2]=a.z; h[3]=a.w;
    h[4]=b.x; h[5]=b.y; h[6]=b.z; h[7]=b.w;
}

// ---- directional term for ONE center pixel (3x3 stencil inside the tile) ----
__device__ __forceinline__ float dirterm(const char* sF, const int* sLab,
                                         const int* __restrict__ labels,
                                         const int* __restrict__ dirs,
                                         const u32 cv[8], int srow, int xc,
                                         int pix) {
    float dt[NB]; bool mk[NB]; float S = 0.f;
#pragma unroll
    for (int k = 0; k < NB; k++) {
        int dik = dirs[(k * 2 + 0) * HWSZ + pix];
        int djk = dirs[(k * 2 + 1) * HWSZ + pix];
        int sl = srow + dik;
        int x  = xc + djk;
        u32 nv[8]; load16h(sF + sl * ROWB + (x & 1) * POFF, x >> 1, nv);
        dt[k] = dot16h(cv, nv);              // log2-scaled logit
        int lbn = sLab[sl * LROW + (x & 1) * LPAR + (x >> 1)];
        mk[k] = (labels[k * HWSZ + pix] == lbn);
        S += mk[k] ? ex2f(dt[k]) : 0.f;
    }
    float logS = __logf(S + EPSV);
    float s = 0.f;
#pragma unroll
    for (int k = 0; k < NB; k++)
        s += mk[k] ? (logS - LN2F * dt[k]) : __int_as_float(0x7f800000);
    return s;
}

// ---------------------------------------------------------------------------
// Single fused kernel. Block = (n, 8 center rows, 64-col quarter), 128 thr,
// 2x2 quad per thread. Halo 18 rows x 76 cols -> 49.2 KB smem, 3 blocks/SM
// (register headroom ~170 so ptxas can pipeline more neighbor chains).
// Halo fill normalizes raw fp32 features in-register (== old k_norm math).
// ---------------------------------------------------------------------------
__global__ void __launch_bounds__(128, 3)
k_local(const float* __restrict__ feat, const int* __restrict__ labels,
        const int* __restrict__ dirs, float* __restrict__ out) {
    extern __shared__ char sm[];
    char* sF   = sm;                      // 18 * 2432 = 43776 B
    int*  sLab = (int*)(sm + 18 * ROWB);  // 18 * 76 ints = 5472 B

    const int bx  = blockIdx.x;           // 0..511
    const int n   = bx >> 7;
    const int rem = bx & 127;
    const int i0  = (rem >> 2) << 3;      // first center row (mult of 8)
    const int hq  = rem & 3;              // which 64-col quarter
    const int cb  = hq * 64 - 6;          // tile base col (global)
    const int t   = threadIdx.x;

    // ---- fill halo: 18 rows x 76 cols; normalize+quantize inline ----
    {
        const float* fbase = feat + (size_t)n * CH * HWSZ;
#pragma unroll 1
        for (int k = 0; k < 11; k++) {
            int lin = t + (k << 7);           // need 1368
            if (lin < 1368) {
                int rr = lin / 76;
                int x  = lin - rr * 76;
                int row = i0 - 5 + rr;
                int g   = cb + x;
                if ((unsigned)row < 256u && (unsigned)g < 256u) {
                    const float* p = fbase + (row << 8) + g;
                    float v[CH]; float ss = 0.f;
#pragma unroll
                    for (int c = 0; c < CH; c++) {
                        v[c] = p[(size_t)c * HWSZ];
                        ss = fmaf(v[c], v[c], ss);
                    }
                    float inv = 1.0f / fmaxf(sqrtf(ss), 1e-12f);
                    u32 h[8];
#pragma unroll
                    for (int c2 = 0; c2 < 8; c2++) {
                        __half2 hh = __floats2half2_rn(v[c2*2] * inv,
                                                       v[c2*2+1] * inv);
                        h[c2] = *(u32*)&hh;
                    }
                    char* dst = sF + rr * ROWB + (x & 1) * POFF + ((x >> 1) << 4);
                    *(uint4*)(dst)        = make_uint4(h[0], h[1], h[2], h[3]);
                    *(uint4*)(dst + CHNK) = make_uint4(h[4], h[5], h[6], h[7]);
                }
            }
        }
        const int* ls = labels + n * HWSZ;
#pragma unroll
        for (int k = 0; k < 11; k++) {
            int lin = t + (k << 7);           // need 1368
            if (lin < 1368) {
                int rr = lin / 76;
                int x  = lin - rr * 76;
                int row = i0 - 5 + rr;
                int g   = cb + x;
                bool ok = ((unsigned)row < 256u) && ((unsigned)g < 256u);
                sLab[rr * LROW + (x & 1) * LPAR + (x >> 1)] =
                    ok ? ls[(row << 8) + g] : (int)0x80000000;
            }
        }
    }
    __syncthreads();

    const int rp = t >> 5;               // 0..3 (warp-uniform)
    const int cp = t & 31;               // col pair 0..31
    const int tc = cp + 3;               // center parity index
    const int sA = 2 * rp + 5;
    const int sB = sA + 1;

    u32 cvAe[8], cvAo[8], cvBe[8], cvBo[8];
    load16h(sF + sA * ROWB,        tc, cvAe);
    load16h(sF + sA * ROWB + POFF, tc, cvAo);
    load16h(sF + sB * ROWB,        tc, cvBe);
    load16h(sF + sB * ROWB + POFF, tc, cvBo);
    __half2 kt = __floats2half2_rn(LOG2E_T, LOG2E_T);
    u32 kt2 = *(u32*)&kt;
    scale16h(cvAe, kt2); scale16h(cvAo, kt2);
    scale16h(cvBe, kt2); scale16h(cvBo, kt2);
    const int clAe = sLab[sA * LROW + tc];
    const int clAo = sLab[sA * LROW + LPAR + tc];
    const int clBe = sLab[sB * LROW + tc];
    const int clBo = sLab[sB * LROW + LPAR + tc];

    u64 SDAe = 0, SDAo = 0, SDBe = 0, SDBo = 0;   // packed {S, D}
    int MAe = 0, MAo = 0, MBe = 0, MBo = 0;

    // ================= v = 0 peel: A-centers only =================
    {
        int s   = 2 * rp;                  // slot 0..6
        int row = i0 - 5 + s;
        if (row >= 0) {                    // warp-uniform
            const char* rowE = sF + s * ROWB;
            const char* rowO = rowE + POFF;
            const int* labE = sLab + s * LROW;
            const int* labO = labE + LPAR;
#pragma unroll
            for (int u = 0; u < 6; u++) {
                int e = cp + 1 + u;
                u32 nv[8]; load16h(rowE, e, nv);
                int lb = labE[e];
                float dAo = dot16h(cvAo, nv);
                float eAo = ex2f(dAo);
                if (lb == clAo) { SDAo = f2add(SDAo, pack2(eAo, dAo)); MAo++; }
                if (u != 5) {
                    float dAe = dot16h(cvAe, nv);
                    float eAe = ex2f(dAe);
                    if (lb == clAe) { SDAe = f2add(SDAe, pack2(eAe, dAe)); MAe++; }
                }
            }
#pragma unroll
            for (int u = 0; u < 6; u++) {
                int o = cp + u;
                u32 nv[8]; load16h(rowO, o, nv);
                int lb = labO[o];
                float dAe = dot16h(cvAe, nv);
                float eAe = ex2f(dAe);
                if (lb == clAe) { SDAe = f2add(SDAe, pack2(eAe, dAe)); MAe++; }
                if (u != 0) {
                    float dAo = dot16h(cvAo, nv);
                    float eAo = ex2f(dAo);
                    if (lb == clAo) { SDAo = f2add(SDAo, pack2(eAo, dAo)); MAo++; }
                }
            }
        }
    }

    // ================= main loop v = 1..10: all four centers =================
#pragma unroll 1
    for (int v = 1; v <= 10; v++) {
        int s   = 2 * rp + v;
        int row = i0 - 5 + s;
        if ((unsigned)row >= 256u) continue;   // warp-uniform
        const char* rowE = sF + s * ROWB;
        const char* rowO = rowE + POFF;
        const int* labE = sLab + s * LROW;
        const int* labO = labE + LPAR;

        // even-pixel neighbors
#pragma unroll
        for (int u = 0; u < 6; u++) {
            int e = cp + 1 + u;
            u32 nv[8]; load16h(rowE, e, nv);
            int lb = labE[e];
            {
                float dAo = dot16h(cvAo, nv);
                float dBo = dot16h(cvBo, nv);
                float eAo = ex2f(dAo), eBo = ex2f(dBo);
                if (lb == clAo) { SDAo = f2add(SDAo, pack2(eAo, dAo)); MAo++; }
                if (lb == clBo) { SDBo = f2add(SDBo, pack2(eBo, dBo)); MBo++; }
            }
            if (u != 5) {
                float dAe = dot16h(cvAe, nv);
                float dBe = dot16h(cvBe, nv);
                float eAe = ex2f(dAe), eBe = ex2f(dBe);
                if (lb == clAe) { SDAe = f2add(SDAe, pack2(eAe, dAe)); MAe++; }
                if (lb == clBe) { SDBe = f2add(SDBe, pack2(eBe, dBe)); MBe++; }
            }
        }
        // odd-pixel neighbors
#pragma unroll
        for (int u = 0; u < 6; u++) {
            int o = cp + u;
            u32 nv[8]; load16h(rowO, o, nv);
            int lb = labO[o];
            {
                float dAe = dot16h(cvAe, nv);
                float dBe = dot16h(cvBe, nv);
                float eAe = ex2f(dAe), eBe = ex2f(dBe);
                if (lb == clAe) { SDAe = f2add(SDAe, pack2(eAe, dAe)); MAe++; }
                if (lb == clBe) { SDBe = f2add(SDBe, pack2(eBe, dBe)); MBe++; }
            }
            if (u != 0) {
                float dAo = dot16h(cvAo, nv);
                float dBo = dot16h(cvBo, nv);
                float eAo = ex2f(dAo), eBo = ex2f(dBo);
                if (lb == clAo) { SDAo = f2add(SDAo, pack2(eAo, dAo)); MAo++; }
                if (lb == clBo) { SDBo = f2add(SDBo, pack2(eBo, dBo)); MBo++; }
            }
        }
    }

    // ================= v = 11 peel: B-centers only =================
    {
        int s   = 2 * rp + 11;             // slot 11..17
        int row = i0 - 5 + s;
        if (row < 256) {                   // warp-uniform
            const char* rowE = sF + s * ROWB;
            const char* rowO = rowE + POFF;
            const int* labE = sLab + s * LROW;
            const int* labO = labE + LPAR;
#pragma unroll
            for (int u = 0; u < 6; u++) {
                int e = cp + 1 + u;
                u32 nv[8]; load16h(rowE, e, nv);
                int lb = labE[e];
                float dBo = dot16h(cvBo, nv);
                float eBo = ex2f(dBo);
                if (lb == clBo) { SDBo = f2add(SDBo, pack2(eBo, dBo)); MBo++; }
                if (u != 5) {
                    float dBe = dot16h(cvBe, nv);
                    float eBe = ex2f(dBe);
                    if (lb == clBe) { SDBe = f2add(SDBe, pack2(eBe, dBe)); MBe++; }
                }
            }
#pragma unroll
            for (int u = 0; u < 6; u++) {
                int o = cp + u;
                u32 nv[8]; load16h(rowO, o, nv);
                int lb = labO[o];
                float dBe = dot16h(cvBe, nv);
                float eBe = ex2f(dBe);
                if (lb == clBe) { SDBe = f2add(SDBe, pack2(eBe, dBe)); MBe++; }
                if (u != 0) {
                    float dBo = dot16h(cvBo, nv);
                    float eBo = ex2f(dBo);
                    if (lb == clBo) { SDBo = f2add(SDBo, pack2(eBo, dBo)); MBo++; }
                }
            }
        }
    }

    float SAe, DAe, SAo, DAo, SBe, DBe, SBo, DBo;
    unpack2(SDAe, SAe, DAe);  unpack2(SDAo, SAo, DAo);
    unpack2(SDBe, SBe, DBe);  unpack2(SDBo, SBo, DBo);

    float cAe = fmaf((float)MAe, __logf(SAe + EPSV), -LN2F * DAe);
    float cAo = fmaf((float)MAo, __logf(SAo + EPSV), -LN2F * DAo);
    float cBe = fmaf((float)MBe, __logf(SBe + EPSV), -LN2F * DBe);
    float cBo = fmaf((float)MBo, __logf(SBo + EPSV), -LN2F * DBo);
    int ciA = i0 + 2 * rp, ciB = ciA + 1;
    int j0  = hq * 64 + 2 * cp, j1 = j0 + 1;
    float chA = (float)(11 - max(0, 5 - ciA) - max(0, ciA - 250));
    float chB = (float)(11 - max(0, 5 - ciB) - max(0, ciB - 250));
    float cw0 = (float)(11 - max(0, 5 - j0)  - max(0, j0  - 250));
    float cw1 = (float)(11 - max(0, 5 - j1)  - max(0, j1  - 250));
    float val = (cAe / (chA * cw0) + cAo / (chA * cw1)
               + cBe / (chB * cw0) + cBo / (chB * cw1)) * (1.0f / (4.0f * 65536.0f));

    // ---- directional term for this thread's 4 pixels (3x3 stencil in tile) --
    {
        float ds = dirterm(sF, sLab, labels, dirs, cvAe, sA, 2*cp + 6, (ciA << 8) + j0)
                 + dirterm(sF, sLab, labels, dirs, cvAo, sA, 2*cp + 7, (ciA << 8) + j1)
                 + dirterm(sF, sLab, labels, dirs, cvBe, sB, 2*cp + 6, (ciB << 8) + j0)
                 + dirterm(sF, sLab, labels, dirs, cvBo, sB, 2*cp + 7, (ciB << 8) + j1);
        val += ds * (1.0f / (16.0f * 65536.0f));
    }

    // ---- block reduce + last-finishing block folds the final sum ----
    __shared__ float wred[4];
    __shared__ bool  slast;
#pragma unroll
    for (int o = 16; o > 0; o >>= 1) val += __shfl_down_sync(0xffffffffu, val, o);
    if ((t & 31) == 0) wred[t >> 5] = val;
    __syncthreads();
    if (t == 0) {
        g_lp[bx] = (wred[0] + wred[1]) + (wred[2] + wred[3]);
        __threadfence();
        unsigned old = atomicAdd(&g_ctr, 1u);
        slast = (old == 511u);
    }
    __syncthreads();

    if (slast) {   // deterministic final reduction over 512 partials
        float v = g_lp[t] + g_lp[t + 128] + g_lp[t + 256] + g_lp[t + 384];
#pragma unroll
        for (int o = 16; o > 0; o >>= 1) v += __shfl_down_sync(0xffffffffu, v, o);
        if ((t & 31) == 0) wred[t >> 5] = v;
        __syncthreads();
        if (t == 0) {
            out[0] = (wred[0] + wred[1]) + (wred[2] + wred[3]);
            g_ctr = 0;   // reset for next graph replay
        }
    }
}

// ---------------------------------------------------------------------------
extern "C" void kernel_launch(void* const* d_in, const int* in_sizes, int n_in,
                              void* d_out, int out_size) {
    const float* feat   = (const float*)d_in[0];
    const int*   labels = (const int*)d_in[1];
    const int*   dirs   = (const int*)d_in[2];
    float* out = (float*)d_out;

    const int smem = 18 * ROWB + 18 * LROW * 4;   // 43776 + 5472 = 49248 B
    cudaFuncSetAttribute(k_local, cudaFuncAttributeMaxDynamicSharedMemorySize, smem);

    k_local<<<512, 128, smem>>>(feat, labels, dirs, out);
}